// round 2
// baseline (speedup 1.0000x reference)
#include <cuda_runtime.h>
#include <cstdint>
#include <cstddef>

#define D 128
#define TILE_ROWS 64
#define GEMM_THREADS 512

// Scratch for message-transformed features (allocation-free rule: device globals)
__device__ float g_U2I[100000 * 128];  // user_features @ W_u2i^T  (no bias)
__device__ float g_I2U[50000 * 128];   // item_features @ W_i2u^T  (no bias)

__device__ __forceinline__ unsigned long long pack2(float a, float b) {
    unsigned long long r;
    asm("mov.b64 %0, {%1, %2};" : "=l"(r) : "f"(a), "f"(b));
    return r;
}
__device__ __forceinline__ void fma2(unsigned long long& acc, unsigned long long x, unsigned long long w) {
    asm("fma.rn.f32x2 %0, %1, %2, %0;" : "+l"(acc) : "l"(x), "l"(w));
}
__device__ __forceinline__ float2 unpack2(unsigned long long v) {
    float2 f;
    asm("mov.b64 {%0, %1}, %2;" : "=f"(f.x), "=f"(f.y) : "l"(v));
    return f;
}

// Persistent dual-output GEMM, 16 warps with 2-D warp tiling:
//   warp_half = wid & 1  : 0 -> Yself (Wa, +bias), 1 -> Ymsg (Wb, no bias)
//   warp_row  = wid >> 1 : 8 rows of the 64-row tile
// Each warp computes 8 rows x 128 outs of ONE half -> W smem traffic
// unchanged vs 8-warp version, but 2x eligible warps per SMSP.
// smem: Wt[128][256] (k-major, Wa outs 0..127, Wb outs 128..255) + Xs[64][128]
extern __shared__ float smem_dyn[];

__global__ __launch_bounds__(GEMM_THREADS, 1)
void gemm_dual(const float* __restrict__ X, int nrows,
               const float* __restrict__ Wa, const float* __restrict__ ba,
               const float* __restrict__ Wb,
               float* __restrict__ Yself, float* __restrict__ Ymsg)
{
    float* Wt = smem_dyn;             // 128*256 floats
    float* Xs = smem_dyn + 128 * 256; // 64*128 floats
    const int tid   = threadIdx.x;
    const int lane  = tid & 31;
    const int wid   = tid >> 5;
    const int half  = wid & 1;        // 0: self(Wa)+bias, 1: msg(Wb)
    const int rbase = (wid >> 1) * 8; // 8 rows per warp-row-group
    const int obase = half * 128 + lane * 4; // smem out column
    const int ocol  = lane * 4;       // output column in the 128-wide result

    // Load W transposed into smem. Consecutive threads -> consecutive o.
    for (int i = tid; i < 128 * 128; i += GEMM_THREADS) {
        int k = i >> 7, o = i & 127;
        Wt[k * 256 + o]       = Wa[o * 128 + k];
        Wt[k * 256 + 128 + o] = Wb[o * 128 + k];
    }
    float4 bias = make_float4(0.f, 0.f, 0.f, 0.f);
    if (half == 0) bias = *(const float4*)&ba[ocol];

    float* __restrict__ Yout = (half == 0) ? Yself : Ymsg;

    const int ntiles = (nrows + TILE_ROWS - 1) / TILE_ROWS;

    for (int tile = blockIdx.x; tile < ntiles; tile += gridDim.x) {
        const int row0 = tile * TILE_ROWS;
        __syncthreads();  // previous tile's readers done (also covers W load on iter 0)

        // Cooperative X tile load (zero-pad tail rows)
        for (int i = tid; i < TILE_ROWS * 32; i += GEMM_THREADS) {
            int r = i >> 5, q = i & 31;
            float4 v = make_float4(0.f, 0.f, 0.f, 0.f);
            if (row0 + r < nrows)
                v = *(const float4*)&X[(size_t)(row0 + r) * D + q * 4];
            *(float4*)&Xs[r * D + q * 4] = v;
        }
        __syncthreads();

        unsigned long long acc[8][2];
        #pragma unroll
        for (int r = 0; r < 8; r++) { acc[r][0] = 0ull; acc[r][1] = 0ull; }

        #pragma unroll 4
        for (int k = 0; k < D; k += 4) {
            ulonglong2 w[4];
            #pragma unroll
            for (int j = 0; j < 4; j++)
                w[j] = *(const ulonglong2*)&Wt[(k + j) * 256 + obase];
            #pragma unroll
            for (int r = 0; r < 8; r++) {
                const float4 xv = *(const float4*)&Xs[(rbase + r) * D + k];
                unsigned long long xx;
                xx = pack2(xv.x, xv.x);
                fma2(acc[r][0], xx, w[0].x); fma2(acc[r][1], xx, w[0].y);
                xx = pack2(xv.y, xv.y);
                fma2(acc[r][0], xx, w[1].x); fma2(acc[r][1], xx, w[1].y);
                xx = pack2(xv.z, xv.z);
                fma2(acc[r][0], xx, w[2].x); fma2(acc[r][1], xx, w[2].y);
                xx = pack2(xv.w, xv.w);
                fma2(acc[r][0], xx, w[3].x); fma2(acc[r][1], xx, w[3].y);
            }
        }

        #pragma unroll
        for (int r = 0; r < 8; r++) {
            const int row = row0 + rbase + r;
            if (row < nrows) {
                float2 a0 = unpack2(acc[r][0]), a1 = unpack2(acc[r][1]);
                *(float4*)&Yout[(size_t)row * D + ocol] =
                    make_float4(a0.x + bias.x, a0.y + bias.y, a1.x + bias.z, a1.y + bias.w);
            }
        }
    }
}

// One warp per edge: gather transformed row, add bias, vector-reduce onto target.
__global__ void scatter_k(const int* __restrict__ eu, const int* __restrict__ ei,
                          const float* __restrict__ bu2i, const float* __restrict__ bi2u,
                          float* __restrict__ user_out, float* __restrict__ item_out, int E)
{
    const int lane = threadIdx.x & 31;
    const int e = (blockIdx.x * blockDim.x + threadIdx.x) >> 5;
    if (e >= E) return;
    const int off = lane * 4;
    const float4 bu = *(const float4*)&bu2i[off];
    const float4 bi = *(const float4*)&bi2u[off];

    const int u  = __ldg(&eu[e]);
    const int it = __ldg(&ei[e]);

    // user -> item
    float4 mu = *(const float4*)&g_U2I[(size_t)u * D + off];
    float* dstI = &item_out[(size_t)it * D + off];
    asm volatile("red.global.add.v4.f32 [%0], {%1,%2,%3,%4};" ::
        "l"(dstI),
        "f"(mu.x + bu.x), "f"(mu.y + bu.y), "f"(mu.z + bu.z), "f"(mu.w + bu.w)
        : "memory");

    // item -> user
    float4 mi = *(const float4*)&g_I2U[(size_t)it * D + off];
    float* dstU = &user_out[(size_t)u * D + off];
    asm volatile("red.global.add.v4.f32 [%0], {%1,%2,%3,%4};" ::
        "l"(dstU),
        "f"(mi.x + bi.x), "f"(mi.y + bi.y), "f"(mi.z + bi.z), "f"(mi.w + bi.w)
        : "memory");
}

extern "C" void kernel_launch(void* const* d_in, const int* in_sizes, int n_in,
                              void* d_out, int out_size)
{
    const float* user_feat = (const float*)d_in[0];
    const float* item_feat = (const float*)d_in[1];
    const int*   edges     = (const int*)d_in[2];
    const float* W_user = (const float*)d_in[3];
    const float* b_user = (const float*)d_in[4];
    const float* W_item = (const float*)d_in[5];
    const float* b_item = (const float*)d_in[6];
    const float* W_u2i  = (const float*)d_in[7];
    const float* b_u2i  = (const float*)d_in[8];
    const float* W_i2u  = (const float*)d_in[9];
    const float* b_i2u  = (const float*)d_in[10];

    const int nU = in_sizes[0] / D;
    const int nI = in_sizes[1] / D;
    const int E  = in_sizes[2] / 2;

    float* user_out = (float*)d_out;
    float* item_out = (float*)d_out + (size_t)nU * D;

    float* u2i_ptr = nullptr;
    float* i2u_ptr = nullptr;
    cudaGetSymbolAddress((void**)&u2i_ptr, g_U2I);
    cudaGetSymbolAddress((void**)&i2u_ptr, g_I2U);

    const int smem_bytes = (128 * 256 + TILE_ROWS * D) * sizeof(float); // 163840
    cudaFuncSetAttribute(gemm_dual, cudaFuncAttributeMaxDynamicSharedMemorySize, smem_bytes);

    const int grid_gemm = 152;  // persistent, 1 block/SM (smem-limited)

    // self-transform + message-transform for users and items (bias-free message path)
    gemm_dual<<<grid_gemm, GEMM_THREADS, smem_bytes>>>(
        user_feat, nU, W_user, b_user, W_u2i, user_out, u2i_ptr);
    gemm_dual<<<grid_gemm, GEMM_THREADS, smem_bytes>>>(
        item_feat, nI, W_item, b_item, W_i2u, item_out, i2u_ptr);

    // edge scatter: one warp per edge, both directions, bias folded in
    const int warps_per_block = 256 / 32;
    const int grid_sc = (E + warps_per_block - 1) / warps_per_block;
    scatter_k<<<grid_sc, 256>>>(
        edges, edges + E, b_u2i, b_i2u, user_out, item_out, E);
}

// round 4
// speedup vs baseline: 1.1729x; 1.1729x over previous
#include <cuda_runtime.h>
#include <cstdint>
#include <cstddef>

#define D 128
#define TILE_ROWS 64
#define GEMM_THREADS 256   // 8 warps: wm = wid&1 (32-row half), wn = wid>>1 (64-col quarter)

// Scratch for message-transformed features (allocation-free rule: device globals)
__device__ float g_U2I[100000 * 128];  // user_features @ W_u2i^T  (no bias)
__device__ float g_I2U[50000 * 128];   // item_features @ W_i2u^T  (no bias)

__device__ __forceinline__ float tf32r(float x) {
    float r;
    asm("cvt.rna.tf32.f32 %0, %1;" : "=f"(r) : "f"(x));
    return r;
}

__device__ __forceinline__ void mma_tf32(float* c, const uint32_t* a, uint32_t b0, uint32_t b1) {
    asm volatile(
        "mma.sync.aligned.m16n8k8.row.col.f32.tf32.tf32.f32 "
        "{%0,%1,%2,%3}, {%4,%5,%6,%7}, {%8,%9}, {%0,%1,%2,%3};"
        : "+f"(c[0]), "+f"(c[1]), "+f"(c[2]), "+f"(c[3])
        : "r"(a[0]), "r"(a[1]), "r"(a[2]), "r"(a[3]), "r"(b0), "r"(b1));
}

// smem layout:
//   Wfrag: 16 ksteps x 32 n8-tiles x 32 lanes x float2  = 131072 B at offset 0
//          frag (kstep, nt): b0 = W'(k=kstep*8+t, o=nt*8+g), b1 = W'(k+4, o)
//          where g = lane>>2, t = lane&3, W' = tf32-rounded [Wa ; Wb] (o<128 -> Wa)
//   Xs:    64 rows x 132 floats (pad 4 kills bank conflicts)  = 33792 B at 131072
#define XS_OFF_F 32768          // float index of Xs
#define XS_LD    132
#define SMEM_BYTES (131072 + 64 * XS_LD * 4)

extern __shared__ __align__(16) float smem_f[];

__global__ __launch_bounds__(GEMM_THREADS, 1)
void gemm_mma(const float* __restrict__ X, int nrows,
              const float* __restrict__ Wa, const float* __restrict__ ba,
              const float* __restrict__ Wb,
              float* __restrict__ Yself, float* __restrict__ Ymsg)
{
    float2* Wfrag = (float2*)smem_f;
    float*  Xs    = smem_f + XS_OFF_F;

    const int tid  = threadIdx.x;
    const int lane = tid & 31;
    const int wid  = tid >> 5;
    const int wm   = wid & 1;        // row half within 64-row tile
    const int wn   = wid >> 1;       // 64-col quarter within 256 outs
    const int g    = lane >> 2;      // groupID
    const int t    = lane & 3;       // thread-in-group

    // ---- Build W fragments once (tf32-rounded, fragment-native layout) ----
    for (int i = tid; i < 16 * 32 * 32; i += GEMM_THREADS) {
        const int l  = i & 31;
        const int nt = (i >> 5) & 31;
        const int ks = i >> 10;
        const int o  = nt * 8 + (l >> 2);
        const int k  = ks * 8 + (l & 3);
        const float* Wsrc = (o < 128) ? (Wa + (size_t)o * 128) : (Wb + (size_t)(o - 128) * 128);
        Wfrag[i] = make_float2(tf32r(Wsrc[k]), tf32r(Wsrc[k + 4]));
    }

    // ---- Bias (only the Yself-column warps need it) ----
    float2 bias2[8];
    if (wn < 2) {
        #pragma unroll
        for (int nt = 0; nt < 8; nt++) {
            const int col = wn * 64 + nt * 8 + t * 2;
            bias2[nt] = make_float2(ba[col], ba[col + 1]);
        }
    }

    const int ntiles = (nrows + TILE_ROWS - 1) / TILE_ROWS;

    for (int tile = blockIdx.x; tile < ntiles; tile += gridDim.x) {
        const int row0 = tile * TILE_ROWS;
        __syncthreads();  // previous tile's Xs readers done (covers Wfrag build on iter 0)

        // ---- Stage X tile (tf32-rounded, zero-pad tail rows) ----
        for (int i = tid; i < TILE_ROWS * 32; i += GEMM_THREADS) {
            const int r = i >> 5, q = i & 31;
            float4 v = make_float4(0.f, 0.f, 0.f, 0.f);
            if (row0 + r < nrows) {
                v = *(const float4*)&X[(size_t)(row0 + r) * D + q * 4];
                v.x = tf32r(v.x); v.y = tf32r(v.y); v.z = tf32r(v.z); v.w = tf32r(v.w);
            }
            *(float4*)&Xs[r * XS_LD + q * 4] = v;
        }
        __syncthreads();

        // ---- MMA mainloop: warp computes 32 rows x 64 cols ----
        float acc[2][8][4];
        #pragma unroll
        for (int mt = 0; mt < 2; mt++)
            #pragma unroll
            for (int nt = 0; nt < 8; nt++)
                #pragma unroll
                for (int j = 0; j < 4; j++) acc[mt][nt][j] = 0.f;

        #pragma unroll 2
        for (int ks = 0; ks < 16; ks++) {
            const int k0 = ks * 8;
            uint32_t a[2][4];
            #pragma unroll
            for (int mt = 0; mt < 2; mt++) {
                const int row = wm * 32 + mt * 16 + g;
                a[mt][0] = __float_as_uint(Xs[row * XS_LD + k0 + t]);
                a[mt][1] = __float_as_uint(Xs[(row + 8) * XS_LD + k0 + t]);
                a[mt][2] = __float_as_uint(Xs[row * XS_LD + k0 + t + 4]);
                a[mt][3] = __float_as_uint(Xs[(row + 8) * XS_LD + k0 + t + 4]);
            }
            #pragma unroll
            for (int nt = 0; nt < 8; nt++) {
                const float2 b = Wfrag[(size_t)(ks * 32 + wn * 8 + nt) * 32 + lane];
                const uint32_t b0 = __float_as_uint(b.x);
                const uint32_t b1 = __float_as_uint(b.y);
                mma_tf32(acc[0][nt], a[0], b0, b1);
                mma_tf32(acc[1][nt], a[1], b0, b1);
            }
        }

        // ---- Epilogue: write Yself (+bias) or Ymsg ----
        #pragma unroll
        for (int mt = 0; mt < 2; mt++) {
            const int r0 = row0 + wm * 32 + mt * 16 + g;   // c0,c1 row
            const int r1 = r0 + 8;                         // c2,c3 row
            #pragma unroll
            for (int nt = 0; nt < 8; nt++) {
                const int colg = wn * 64 + nt * 8 + t * 2;
                if (wn < 2) {
                    if (r0 < nrows)
                        *(float2*)&Yself[(size_t)r0 * D + colg] =
                            make_float2(acc[mt][nt][0] + bias2[nt].x,
                                        acc[mt][nt][1] + bias2[nt].y);
                    if (r1 < nrows)
                        *(float2*)&Yself[(size_t)r1 * D + colg] =
                            make_float2(acc[mt][nt][2] + bias2[nt].x,
                                        acc[mt][nt][3] + bias2[nt].y);
                } else {
                    const int colm = colg - 128;
                    if (r0 < nrows)
                        *(float2*)&Ymsg[(size_t)r0 * D + colm] =
                            make_float2(acc[mt][nt][0], acc[mt][nt][1]);
                    if (r1 < nrows)
                        *(float2*)&Ymsg[(size_t)r1 * D + colm] =
                            make_float2(acc[mt][nt][2], acc[mt][nt][3]);
                }
            }
        }
    }
}

// One warp per edge: gather transformed row, add bias, vector-reduce onto target.
__global__ void scatter_k(const int* __restrict__ eu, const int* __restrict__ ei,
                          const float* __restrict__ bu2i, const float* __restrict__ bi2u,
                          float* __restrict__ user_out, float* __restrict__ item_out, int E)
{
    const int lane = threadIdx.x & 31;
    const int e = (blockIdx.x * blockDim.x + threadIdx.x) >> 5;
    if (e >= E) return;
    const int off = lane * 4;
    const float4 bu = *(const float4*)&bu2i[off];
    const float4 bi = *(const float4*)&bi2u[off];

    const int u  = __ldg(&eu[e]);
    const int it = __ldg(&ei[e]);

    float4 mu = *(const float4*)&g_U2I[(size_t)u * D + off];
    float* dstI = &item_out[(size_t)it * D + off];
    asm volatile("red.global.add.v4.f32 [%0], {%1,%2,%3,%4};" ::
        "l"(dstI),
        "f"(mu.x + bu.x), "f"(mu.y + bu.y), "f"(mu.z + bu.z), "f"(mu.w + bu.w)
        : "memory");

    float4 mi = *(const float4*)&g_I2U[(size_t)it * D + off];
    float* dstU = &user_out[(size_t)u * D + off];
    asm volatile("red.global.add.v4.f32 [%0], {%1,%2,%3,%4};" ::
        "l"(dstU),
        "f"(mi.x + bi.x), "f"(mi.y + bi.y), "f"(mi.z + bi.z), "f"(mi.w + bi.w)
        : "memory");
}

extern "C" void kernel_launch(void* const* d_in, const int* in_sizes, int n_in,
                              void* d_out, int out_size)
{
    const float* user_feat = (const float*)d_in[0];
    const float* item_feat = (const float*)d_in[1];
    const int*   edges     = (const int*)d_in[2];
    const float* W_user = (const float*)d_in[3];
    const float* b_user = (const float*)d_in[4];
    const float* W_item = (const float*)d_in[5];
    const float* b_item = (const float*)d_in[6];
    const float* W_u2i  = (const float*)d_in[7];
    const float* b_u2i  = (const float*)d_in[8];
    const float* W_i2u  = (const float*)d_in[9];
    const float* b_i2u  = (const float*)d_in[10];

    const int nU = in_sizes[0] / D;
    const int nI = in_sizes[1] / D;
    const int E  = in_sizes[2] / 2;

    float* user_out = (float*)d_out;
    float* item_out = (float*)d_out + (size_t)nU * D;

    float* u2i_ptr = nullptr;
    float* i2u_ptr = nullptr;
    cudaGetSymbolAddress((void**)&u2i_ptr, g_U2I);
    cudaGetSymbolAddress((void**)&i2u_ptr, g_I2U);

    cudaFuncSetAttribute(gemm_mma, cudaFuncAttributeMaxDynamicSharedMemorySize, SMEM_BYTES);

    gemm_mma<<<152, GEMM_THREADS, SMEM_BYTES>>>(
        user_feat, nU, W_user, b_user, W_u2i, user_out, u2i_ptr);
    gemm_mma<<<152, GEMM_THREADS, SMEM_BYTES>>>(
        item_feat, nI, W_item, b_item, W_i2u, item_out, i2u_ptr);

    const int warps_per_block = 256 / 32;
    const int grid_sc = (E + warps_per_block - 1) / warps_per_block;
    scatter_k<<<grid_sc, 256>>>(edges, edges + E, b_u2i, b_i2u, user_out, item_out, E);
}